// round 2
// baseline (speedup 1.0000x reference)
#include <cuda_runtime.h>
#include <math.h>

#define Bb 2
#define Nn 2048
#define Mm 2048
#define DIMd 512
#define Hh 8
#define DHd 64
#define INNERi 512

// ---------------- scratch (allocation-free) ----------------
__device__ float g_q[Bb * Nn * INNERi];
__device__ float g_k[Bb * Mm * INNERi];
__device__ float g_v[Bb * Nn * INNERi];
__device__ float g_ctx[Bb * Nn * INNERi];

// ---------------- generic 128x128x16 SGEMM ----------------
// MODE 0: C0[row*Cols + col]
// MODE 1: qv split -> cols [0,512) to C0 (ld 512), cols [512,1024) to C1 (ld 512)
// MODE 2: C0[row*Cols + col] + bias[col]
template <int MODE>
__global__ __launch_bounds__(256) void gemm128(
    const float* __restrict__ A, const float* __restrict__ W,
    float* __restrict__ C0, float* __restrict__ C1,
    const float* __restrict__ bias, int Rows, int Cols, int Kd) {
    __shared__ float As[16 * 132];  // transposed A tile, pitch 132 (conflict pad)
    __shared__ float Bs[16 * 128];

    const int tid = threadIdx.x;
    const int tx = tid & 15;
    const int ty = tid >> 4;
    const int row0 = blockIdx.y * 128;
    const int col0 = blockIdx.x * 128;

    float acc[8][8];
#pragma unroll
    for (int i = 0; i < 8; i++)
#pragma unroll
        for (int j = 0; j < 8; j++) acc[i][j] = 0.f;

    for (int k0 = 0; k0 < Kd; k0 += 16) {
#pragma unroll
        for (int i = 0; i < 2; i++) {
            int f = tid + i * 256;
            // A tile: 128 rows x 16 k  (512 float4)
            int r = f >> 2, k4 = f & 3;
            float4 va = *(const float4*)&A[(size_t)(row0 + r) * Kd + k0 + k4 * 4];
            As[(k4 * 4 + 0) * 132 + r] = va.x;
            As[(k4 * 4 + 1) * 132 + r] = va.y;
            As[(k4 * 4 + 2) * 132 + r] = va.z;
            As[(k4 * 4 + 3) * 132 + r] = va.w;
            // B tile: 16 k x 128 cols (512 float4)
            int rr = f >> 5, c4 = f & 31;
            float4 vb = *(const float4*)&W[(size_t)(k0 + rr) * Cols + col0 + c4 * 4];
            *(float4*)&Bs[rr * 128 + c4 * 4] = vb;
        }
        __syncthreads();
#pragma unroll
        for (int kk = 0; kk < 16; kk++) {
            float4 a0 = *(float4*)&As[kk * 132 + ty * 8];
            float4 a1 = *(float4*)&As[kk * 132 + ty * 8 + 4];
            float4 b0 = *(float4*)&Bs[kk * 128 + tx * 8];
            float4 b1 = *(float4*)&Bs[kk * 128 + tx * 8 + 4];
            float av[8] = {a0.x, a0.y, a0.z, a0.w, a1.x, a1.y, a1.z, a1.w};
            float bv[8] = {b0.x, b0.y, b0.z, b0.w, b1.x, b1.y, b1.z, b1.w};
#pragma unroll
            for (int i = 0; i < 8; i++)
#pragma unroll
                for (int j = 0; j < 8; j++) acc[i][j] += av[i] * bv[j];
        }
        __syncthreads();
    }

    // epilogue
#pragma unroll
    for (int i = 0; i < 8; i++) {
        int row = row0 + ty * 8 + i;
        if (MODE == 0) {
            float4 o0 = {acc[i][0], acc[i][1], acc[i][2], acc[i][3]};
            float4 o1 = {acc[i][4], acc[i][5], acc[i][6], acc[i][7]};
            *(float4*)&C0[(size_t)row * Cols + col0 + tx * 8] = o0;
            *(float4*)&C0[(size_t)row * Cols + col0 + tx * 8 + 4] = o1;
        } else if (MODE == 1) {
            float* dst = (col0 < INNERi) ? C0 : C1;
            int cb = col0 - ((col0 < INNERi) ? 0 : INNERi);
            float4 o0 = {acc[i][0], acc[i][1], acc[i][2], acc[i][3]};
            float4 o1 = {acc[i][4], acc[i][5], acc[i][6], acc[i][7]};
            *(float4*)&dst[(size_t)row * INNERi + cb + tx * 8] = o0;
            *(float4*)&dst[(size_t)row * INNERi + cb + tx * 8 + 4] = o1;
        } else {
            float4 o0, o1;
            int c = col0 + tx * 8;
            o0.x = acc[i][0] + bias[c + 0];
            o0.y = acc[i][1] + bias[c + 1];
            o0.z = acc[i][2] + bias[c + 2];
            o0.w = acc[i][3] + bias[c + 3];
            o1.x = acc[i][4] + bias[c + 4];
            o1.y = acc[i][5] + bias[c + 5];
            o1.z = acc[i][6] + bias[c + 6];
            o1.w = acc[i][7] + bias[c + 7];
            *(float4*)&C0[(size_t)row * Cols + c] = o0;
            *(float4*)&C0[(size_t)row * Cols + c + 4] = o1;
        }
    }
}

// smem swizzle: row-major [64][64], XOR at 16B granularity (keeps float4 loads)
__device__ __forceinline__ int SW(int r, int c) {
    return r * 64 + (c ^ (((r >> 2) & 7) << 2));
}

// ---------------- fused attention (flash-style, online softmax) ----------------
// block = (n-tile of 64 rows, head h, batch b); 256 threads; 4x4 microtile
__global__ __launch_bounds__(256) void attn_kernel(
    const float* __restrict__ q, const float* __restrict__ k,
    const float* __restrict__ v, const float* __restrict__ am,
    const float* __restrict__ dp, const float* __restrict__ mp,
    float* __restrict__ ctx) {
    extern __shared__ float sm[];
    float* Qt = sm;           // [k][r] swizzled, 4096
    float* Kt = sm + 4096;    // [k][c] swizzled
    float* Vs = sm + 8192;    // [m][d] plain
    float* Pt = sm + 12288;   // [m][r] swizzled

    const int tid = threadIdx.x;
    const int tx = tid & 15;
    const int ty = tid >> 4;
    const int n0 = blockIdx.x * 64;
    const int h = blockIdx.y;
    const int b = blockIdx.z;

    const float sc = 0.125f * dp[0];  // DH^-0.5 * dots_para
    const float mpv = mp[0];

    // Q tile -> Qt transposed
    const float* qb = q + ((size_t)b * Nn + n0) * INNERi + h * DHd;
#pragma unroll
    for (int i = 0; i < 4; i++) {
        int f = tid + i * 256;
        int r = f >> 4, c = (f & 15) * 4;
        float4 vq = *(const float4*)&qb[(size_t)r * INNERi + c];
        Qt[SW(c + 0, r)] = vq.x;
        Qt[SW(c + 1, r)] = vq.y;
        Qt[SW(c + 2, r)] = vq.z;
        Qt[SW(c + 3, r)] = vq.w;
    }

    float mrow[4], lrow[4], acc[4][4];
#pragma unroll
    for (int i = 0; i < 4; i++) {
        mrow[i] = -1e30f;
        lrow[i] = 0.f;
#pragma unroll
        for (int j = 0; j < 4; j++) acc[i][j] = 0.f;
    }

    for (int mt = 0; mt < Mm / 64; mt++) {
        const int m0 = mt * 64;
        const float* kb = k + ((size_t)b * Mm + m0) * INNERi + h * DHd;
        const float* vb = v + ((size_t)b * Mm + m0) * INNERi + h * DHd;
#pragma unroll
        for (int i = 0; i < 4; i++) {
            int f = tid + i * 256;
            int r = f >> 4, c = (f & 15) * 4;
            float4 vk = *(const float4*)&kb[(size_t)r * INNERi + c];
            Kt[SW(c + 0, r)] = vk.x;
            Kt[SW(c + 1, r)] = vk.y;
            Kt[SW(c + 2, r)] = vk.z;
            Kt[SW(c + 3, r)] = vk.w;
            float4 vv = *(const float4*)&vb[(size_t)r * INNERi + c];
            *(float4*)&Vs[r * 64 + c] = vv;
        }
        __syncthreads();

        // S = Q Kt
        float s[4][4];
#pragma unroll
        for (int i = 0; i < 4; i++)
#pragma unroll
            for (int j = 0; j < 4; j++) s[i][j] = 0.f;
#pragma unroll 16
        for (int kk = 0; kk < 64; kk++) {
            float4 a4 = *(float4*)&Qt[SW(kk, ty * 4)];
            float4 b4 = *(float4*)&Kt[SW(kk, tx * 4)];
            float av[4] = {a4.x, a4.y, a4.z, a4.w};
            float bv[4] = {b4.x, b4.y, b4.z, b4.w};
#pragma unroll
            for (int i = 0; i < 4; i++)
#pragma unroll
                for (int j = 0; j < 4; j++) s[i][j] += av[i] * bv[j];
        }

        // scale + attn_mat
        const float* ab =
            am + ((size_t)(b * Hh + h) * Nn + n0 + ty * 4) * Mm + m0 + tx * 4;
#pragma unroll
        for (int i = 0; i < 4; i++) {
            float4 a4 = *(const float4*)&ab[(size_t)i * Mm];
            s[i][0] = s[i][0] * sc + a4.x * mpv;
            s[i][1] = s[i][1] * sc + a4.y * mpv;
            s[i][2] = s[i][2] * sc + a4.z * mpv;
            s[i][3] = s[i][3] * sc + a4.w * mpv;
        }

        // online softmax (row stats duplicated/consistent across tx group)
#pragma unroll
        for (int i = 0; i < 4; i++) {
            float tmax = fmaxf(fmaxf(s[i][0], s[i][1]), fmaxf(s[i][2], s[i][3]));
#pragma unroll
            for (int o = 1; o < 16; o <<= 1)
                tmax = fmaxf(tmax, __shfl_xor_sync(0xffffffffu, tmax, o));
            float mnew = fmaxf(mrow[i], tmax);
            float corr = __expf(mrow[i] - mnew);
            mrow[i] = mnew;
            lrow[i] *= corr;
#pragma unroll
            for (int j = 0; j < 4; j++) acc[i][j] *= corr;
            float rs = 0.f;
#pragma unroll
            for (int j = 0; j < 4; j++) {
                s[i][j] = __expf(s[i][j] - mnew);
                rs += s[i][j];
            }
#pragma unroll
            for (int o = 1; o < 16; o <<= 1)
                rs += __shfl_xor_sync(0xffffffffu, rs, o);
            lrow[i] += rs;
#pragma unroll
            for (int j = 0; j < 4; j++) Pt[SW(tx * 4 + j, ty * 4 + i)] = s[i][j];
        }
        __syncthreads();

        // acc += P V
#pragma unroll 16
        for (int m = 0; m < 64; m++) {
            float4 p4 = *(float4*)&Pt[SW(m, ty * 4)];
            float4 v4 = *(float4*)&Vs[m * 64 + tx * 4];
            float pv[4] = {p4.x, p4.y, p4.z, p4.w};
            float vv[4] = {v4.x, v4.y, v4.z, v4.w};
#pragma unroll
            for (int i = 0; i < 4; i++)
#pragma unroll
                for (int j = 0; j < 4; j++) acc[i][j] += pv[i] * vv[j];
        }
        __syncthreads();
    }

    // epilogue: ctx[b, n, h*64 + d] = acc / l
    float* ob = ctx + ((size_t)b * Nn + n0) * INNERi + h * DHd;
#pragma unroll
    for (int i = 0; i < 4; i++) {
        int r = ty * 4 + i;
        float inv = 1.f / lrow[i];
        float4 o = {acc[i][0] * inv, acc[i][1] * inv, acc[i][2] * inv,
                    acc[i][3] * inv};
        *(float4*)&ob[(size_t)r * INNERi + tx * 4] = o;
    }
}

extern "C" void kernel_launch(void* const* d_in, const int* in_sizes, int n_in,
                              void* d_out, int out_size) {
    const float* x = (const float*)d_in[0];
    const float* x1 = (const float*)d_in[1];
    const float* am = (const float*)d_in[2];
    const float* dp = (const float*)d_in[3];
    const float* mp = (const float*)d_in[4];
    const float* Wqv = (const float*)d_in[5];
    const float* Wk = (const float*)d_in[6];
    const float* Wout = (const float*)d_in[7];
    const float* bout = (const float*)d_in[8];
    float* out = (float*)d_out;

    float *gq, *gk, *gv, *gctx;
    cudaGetSymbolAddress((void**)&gq, g_q);
    cudaGetSymbolAddress((void**)&gk, g_k);
    cudaGetSymbolAddress((void**)&gv, g_v);
    cudaGetSymbolAddress((void**)&gctx, g_ctx);

    const int rows = Bb * Nn;  // 4096

    // qv projection (split epilogue)
    gemm128<1><<<dim3((2 * INNERi) / 128, rows / 128), 256>>>(
        x, Wqv, gq, gv, nullptr, rows, 2 * INNERi, DIMd);
    // k projection
    gemm128<0><<<dim3(INNERi / 128, rows / 128), 256>>>(
        x1, Wk, gk, nullptr, nullptr, rows, INNERi, DIMd);

    // fused attention
    cudaFuncSetAttribute(attn_kernel,
                         cudaFuncAttributeMaxDynamicSharedMemorySize, 65536);
    attn_kernel<<<dim3(Nn / 64, Hh, Bb), 256, 65536>>>(gq, gk, gv, am, dp, mp,
                                                       gctx);

    // output projection + bias
    gemm128<2><<<dim3(DIMd / 128, rows / 128), 256>>>(
        gctx, Wout, out, nullptr, bout, rows, DIMd, DIMd);
}

// round 4
// speedup vs baseline: 2.9254x; 2.9254x over previous
#include <cuda_runtime.h>
#include <cstdint>
#include <math.h>

#define Bb 2
#define Nn 2048
#define Mm 2048
#define DIMd 512
#define Hh 8
#define DHd 64
#define INNERi 512

// ---------------- scratch (allocation-free) ----------------
__device__ float g_x[Bb * Nn * DIMd];    // tf32-rounded x
__device__ float g_x1[Bb * Mm * DIMd];   // tf32-rounded x1
__device__ float g_q[Bb * Nn * INNERi];
__device__ float g_k[Bb * Mm * INNERi];
__device__ float g_v[Bb * Nn * INNERi];
__device__ float g_ctx[Bb * Nn * INNERi];
__device__ float g_wqvt[2 * INNERi * DIMd];
__device__ float g_wkt[INNERi * DIMd];
__device__ float g_wot[DIMd * INNERi];

// ---------------- helpers ----------------
__device__ __forceinline__ float to_tf32(float x) {
    uint32_t r;
    asm("cvt.rna.tf32.f32 %0, %1;" : "=r"(r) : "f"(x));
    return __uint_as_float(r);
}
__device__ __forceinline__ void mma8(float* c, uint32_t a0, uint32_t a1,
                                     uint32_t a2, uint32_t a3, uint32_t b0,
                                     uint32_t b1) {
    asm volatile(
        "mma.sync.aligned.m16n8k8.row.col.f32.tf32.tf32.f32 "
        "{%0,%1,%2,%3}, {%4,%5,%6,%7}, {%8,%9}, {%0,%1,%2,%3};"
        : "+f"(c[0]), "+f"(c[1]), "+f"(c[2]), "+f"(c[3])
        : "r"(a0), "r"(a1), "r"(a2), "r"(a3), "r"(b0), "r"(b1));
}
#define FAU(x) __float_as_uint(x)
#define CPA16(dst, src) \
    asm volatile("cp.async.cg.shared.global [%0], [%1], 16;" ::"r"(dst), "l"(src))
#define CP_COMMIT() asm volatile("cp.async.commit_group;")

// ---------------- prepass: tf32 rounding copy ----------------
__global__ __launch_bounds__(256) void round_copy(const float4* __restrict__ in,
                                                  float4* __restrict__ out, int n4) {
    int i = blockIdx.x * blockDim.x + threadIdx.x;
    if (i < n4) {
        float4 v = in[i];
        v.x = to_tf32(v.x);
        v.y = to_tf32(v.y);
        v.z = to_tf32(v.z);
        v.w = to_tf32(v.w);
        out[i] = v;
    }
}

// ---------------- W transpose + tf32 round: W[K][N] -> Wt[N][K] ----------------
__global__ __launch_bounds__(256) void transposeW(const float* __restrict__ W,
                                                  float* __restrict__ Wt, int K, int N) {
    __shared__ float t[32][33];
    int n0 = blockIdx.x * 32, k0 = blockIdx.y * 32;
    int x = threadIdx.x & 31, y = threadIdx.x >> 5;
#pragma unroll
    for (int i = 0; i < 32; i += 8) t[y + i][x] = W[(size_t)(k0 + y + i) * N + n0 + x];
    __syncthreads();
#pragma unroll
    for (int i = 0; i < 32; i += 8)
        Wt[(size_t)(n0 + y + i) * K + k0 + x] = to_tf32(t[x][y + i]);
}

// ---------------- mma.sync tf32 GEMM: C[Rows x Cols] = A[Rows x K] @ Wt[Cols x K]^T
// MODE 0: plain, output tf32-rounded (k proj)
// MODE 1: qv split -> cols<512 to C0, else C1 (both ld 512), tf32-rounded
// MODE 2: + bias, plain f32 output (final out)
template <int MODE>
__global__ __launch_bounds__(256) void mma_gemm(
    const float* __restrict__ A, const float* __restrict__ Wt,
    float* __restrict__ C0, float* __restrict__ C1,
    const float* __restrict__ bias, int Cols, int Kd) {
    extern __shared__ float sm[];
    // stage s (s=0,1): A tile [128][36] at s*9216, B tile [128][36] at s*9216+4608
    const int tid = threadIdx.x, lane = tid & 31, wid = tid >> 5;
    const int g = lane >> 2, t = lane & 3;
    const int warp_m = wid & 1, warp_n = wid >> 1;
    const int row0 = blockIdx.y * 128, col0 = blockIdx.x * 128;
    const uint32_t smb = (uint32_t)__cvta_generic_to_shared(sm);

    float acc[4][4][4];
#pragma unroll
    for (int i = 0; i < 4; i++)
#pragma unroll
        for (int j = 0; j < 4; j++)
#pragma unroll
            for (int q = 0; q < 4; q++) acc[i][j][q] = 0.f;

    const int nch = Kd / 32;
    auto issue = [&](int c) {
        const int s = c & 1, k0 = c * 32;
        const uint32_t ab = smb + s * 9216 * 4;
        const uint32_t bb = ab + 4608 * 4;
#pragma unroll
        for (int p = 0; p < 4; p++) {
            int idx = tid + p * 256;
            int r = idx >> 3, c4 = idx & 7;
            CPA16(ab + (r * 36 + c4 * 4) * 4, &A[(size_t)(row0 + r) * Kd + k0 + c4 * 4]);
            CPA16(bb + (r * 36 + c4 * 4) * 4, &Wt[(size_t)(col0 + r) * Kd + k0 + c4 * 4]);
        }
        CP_COMMIT();
    };
    issue(0);
    issue(1);

    for (int c = 0; c < nch; c++) {
        if (c + 1 < nch) asm volatile("cp.async.wait_group 1;");
        else asm volatile("cp.async.wait_group 0;");
        __syncthreads();
        const float* As = sm + (c & 1) * 9216;
        const float* Bs = As + 4608;
#pragma unroll
        for (int ks = 0; ks < 4; ks++) {
            const int k0s = ks * 8;
            uint32_t af[4][4], bf[4][2];
#pragma unroll
            for (int mt = 0; mt < 4; mt++) {
                const float* ap = As + (warp_m * 64 + mt * 16 + g) * 36 + k0s + t;
                af[mt][0] = FAU(ap[0]);
                af[mt][1] = FAU(ap[8 * 36]);
                af[mt][2] = FAU(ap[4]);
                af[mt][3] = FAU(ap[8 * 36 + 4]);
            }
#pragma unroll
            for (int nt = 0; nt < 4; nt++) {
                const float* bp = Bs + (warp_n * 32 + nt * 8 + g) * 36 + k0s + t;
                bf[nt][0] = FAU(bp[0]);
                bf[nt][1] = FAU(bp[4]);
            }
#pragma unroll
            for (int mt = 0; mt < 4; mt++)
#pragma unroll
                for (int nt = 0; nt < 4; nt++)
                    mma8(acc[mt][nt], af[mt][0], af[mt][1], af[mt][2], af[mt][3],
                         bf[nt][0], bf[nt][1]);
        }
        __syncthreads();
        if (c + 2 < nch) issue(c + 2);
    }

    // epilogue
#pragma unroll
    for (int mt = 0; mt < 4; mt++) {
#pragma unroll
        for (int nt = 0; nt < 4; nt++) {
            const int r = row0 + warp_m * 64 + mt * 16 + g;
            const int cc = col0 + warp_n * 32 + nt * 8 + 2 * t;
            float v0 = acc[mt][nt][0], v1 = acc[mt][nt][1];
            float v2 = acc[mt][nt][2], v3 = acc[mt][nt][3];
            if (MODE == 2) {
                v0 += bias[cc];
                v1 += bias[cc + 1];
                v2 += bias[cc];
                v3 += bias[cc + 1];
            } else {
                v0 = to_tf32(v0);
                v1 = to_tf32(v1);
                v2 = to_tf32(v2);
                v3 = to_tf32(v3);
            }
            float* dst = C0;
            int c2 = cc, ld = Cols;
            if (MODE == 1) {
                dst = (cc < INNERi) ? C0 : C1;
                c2 = cc & (INNERi - 1);
                ld = INNERi;
            }
            float2 lo = {v0, v1}, hi = {v2, v3};
            *(float2*)&dst[(size_t)r * ld + c2] = lo;
            *(float2*)&dst[(size_t)(r + 8) * ld + c2] = hi;
        }
    }
}

// ---------------- fused attention with mma.sync tf32 ----------------
// block = 128 q-rows x (h, b); 256 threads; warp owns 16 rows.
__global__ __launch_bounds__(256) void attn_mma(
    const float* __restrict__ q, const float* __restrict__ k,
    const float* __restrict__ v, const float* __restrict__ am,
    const float* __restrict__ dp, const float* __restrict__ mp,
    float* __restrict__ ctx) {
    extern __shared__ float sm[];
    // Ks: 2 x [64][68] @ 0 ; Vs: 2 x [64][68] @ 8704 ; Pq: [128][68] @ 17408
    float* Ks = sm;
    float* Vs = sm + 2 * 4352;
    float* Pq = sm + 4 * 4352;

    const int tid = threadIdx.x, lane = tid & 31, wid = tid >> 5;
    const int g = lane >> 2, t = lane & 3;
    const int n0 = blockIdx.x * 128;
    const int h = blockIdx.y, b = blockIdx.z;
    const int rw = wid * 16;
    const float sc = 0.125f * dp[0];
    const float mpv = mp[0];
    const uint32_t smb = (uint32_t)__cvta_generic_to_shared(sm);
    const uint32_t pqb = smb + 4 * 4352 * 4;

    // stage Q tile [128][64] into Pq
    {
        const float* qb = q + ((size_t)(b * Nn) + n0) * INNERi + h * DHd;
#pragma unroll
        for (int p = 0; p < 8; p++) {
            int idx = tid + p * 256;
            int r = idx >> 4, c4 = idx & 15;
            CPA16(pqb + (r * 68 + c4 * 4) * 4, qb + (size_t)r * INNERi + c4 * 4);
        }
        CP_COMMIT();
        asm volatile("cp.async.wait_group 0;");
        __syncthreads();
    }
    uint32_t qf[8][4];
#pragma unroll
    for (int kt = 0; kt < 8; kt++) {
        const float* qp = Pq + (rw + g) * 68 + kt * 8 + t;
        qf[kt][0] = FAU(qp[0]);
        qf[kt][1] = FAU(qp[8 * 68]);
        qf[kt][2] = FAU(qp[4]);
        qf[kt][3] = FAU(qp[8 * 68 + 4]);
    }
    __syncthreads();

    const float* kb = k + (size_t)b * Mm * INNERi + h * DHd;
    const float* vb = v + (size_t)b * Mm * INNERi + h * DHd;
    auto issue = [&](int mt) {
        const int s = mt & 1, m0 = mt * 64;
        const uint32_t kd = smb + s * 4352 * 4;
        const uint32_t vd = smb + (2 + s) * 4352 * 4;
#pragma unroll
        for (int p = 0; p < 4; p++) {
            int idx = tid + p * 256;
            int r = idx >> 4, c4 = idx & 15;
            CPA16(kd + (r * 68 + c4 * 4) * 4, kb + (size_t)(m0 + r) * INNERi + c4 * 4);
            CPA16(vd + (r * 68 + c4 * 4) * 4, vb + (size_t)(m0 + r) * INNERi + c4 * 4);
        }
        CP_COMMIT();
    };
    issue(0);
    issue(1);

    float o[8][4];
#pragma unroll
    for (int i = 0; i < 8; i++)
#pragma unroll
        for (int j = 0; j < 4; j++) o[i][j] = 0.f;
    float m_lo = -1e30f, m_hi = -1e30f, l_lo = 0.f, l_hi = 0.f;

    for (int mt = 0; mt < 32; mt++) {
        if (mt + 1 < 32) asm volatile("cp.async.wait_group 1;");
        else asm volatile("cp.async.wait_group 0;");
        __syncthreads();
        const float* Kc = Ks + (mt & 1) * 4352;
        const float* Vc = Vs + (mt & 1) * 4352;

        // S = Q K^T   (rows rw..rw+15, cols 0..63)
        float s[8][4];
#pragma unroll
        for (int nt = 0; nt < 8; nt++)
#pragma unroll
            for (int j = 0; j < 4; j++) s[nt][j] = 0.f;
#pragma unroll
        for (int kt = 0; kt < 8; kt++) {
#pragma unroll
            for (int nt = 0; nt < 8; nt++) {
                const float* kp = Kc + (nt * 8 + g) * 68 + kt * 8 + t;
                mma8(s[nt], qf[kt][0], qf[kt][1], qf[kt][2], qf[kt][3],
                     FAU(kp[0]), FAU(kp[4]));
            }
        }

        // scale + attn_mat
        const float* ap =
            am + ((size_t)((b * Hh + h) * Nn) + n0 + rw + g) * Mm + mt * 64 + 2 * t;
#pragma unroll
        for (int nt = 0; nt < 8; nt++) {
            float2 alo = *(const float2*)(ap + nt * 8);
            float2 ahi = *(const float2*)(ap + 8 * (size_t)Mm + nt * 8);
            s[nt][0] = s[nt][0] * sc + alo.x * mpv;
            s[nt][1] = s[nt][1] * sc + alo.y * mpv;
            s[nt][2] = s[nt][2] * sc + ahi.x * mpv;
            s[nt][3] = s[nt][3] * sc + ahi.y * mpv;
        }

        // online softmax
        float rlo = -1e30f, rhi = -1e30f;
#pragma unroll
        for (int nt = 0; nt < 8; nt++) {
            rlo = fmaxf(rlo, fmaxf(s[nt][0], s[nt][1]));
            rhi = fmaxf(rhi, fmaxf(s[nt][2], s[nt][3]));
        }
        rlo = fmaxf(rlo, __shfl_xor_sync(0xffffffffu, rlo, 1));
        rlo = fmaxf(rlo, __shfl_xor_sync(0xffffffffu, rlo, 2));
        rhi = fmaxf(rhi, __shfl_xor_sync(0xffffffffu, rhi, 1));
        rhi = fmaxf(rhi, __shfl_xor_sync(0xffffffffu, rhi, 2));
        const float mnl = fmaxf(m_lo, rlo), mnh = fmaxf(m_hi, rhi);
        const float cl = __expf(m_lo - mnl), ch = __expf(m_hi - mnh);
        m_lo = mnl;
        m_hi = mnh;
        float sl = 0.f, sh = 0.f;
#pragma unroll
        for (int nt = 0; nt < 8; nt++) {
            s[nt][0] = __expf(s[nt][0] - mnl);
            s[nt][1] = __expf(s[nt][1] - mnl);
            s[nt][2] = __expf(s[nt][2] - mnh);
            s[nt][3] = __expf(s[nt][3] - mnh);
            sl += s[nt][0] + s[nt][1];
            sh += s[nt][2] + s[nt][3];
        }
        sl += __shfl_xor_sync(0xffffffffu, sl, 1);
        sl += __shfl_xor_sync(0xffffffffu, sl, 2);
        sh += __shfl_xor_sync(0xffffffffu, sh, 1);
        sh += __shfl_xor_sync(0xffffffffu, sh, 2);
        l_lo = l_lo * cl + sl;
        l_hi = l_hi * ch + sh;

        // rescale O, write P (tf32-rounded)
#pragma unroll
        for (int nt = 0; nt < 8; nt++) {
            o[nt][0] *= cl;
            o[nt][1] *= cl;
            o[nt][2] *= ch;
            o[nt][3] *= ch;
            float2 plo = {to_tf32(s[nt][0]), to_tf32(s[nt][1])};
            float2 phi = {to_tf32(s[nt][2]), to_tf32(s[nt][3])};
            *(float2*)(Pq + (rw + g) * 68 + nt * 8 + 2 * t) = plo;
            *(float2*)(Pq + (rw + g + 8) * 68 + nt * 8 + 2 * t) = phi;
        }
        __syncwarp();

        // O += P V
#pragma unroll
        for (int kt = 0; kt < 8; kt++) {
            const float* pp = Pq + (rw + g) * 68 + kt * 8 + t;
            const uint32_t pa0 = FAU(pp[0]), pa1 = FAU(pp[8 * 68]);
            const uint32_t pa2 = FAU(pp[4]), pa3 = FAU(pp[8 * 68 + 4]);
#pragma unroll
            for (int nt = 0; nt < 8; nt++) {
                const float* vp = Vc + (kt * 8 + t) * 68 + nt * 8 + g;
                mma8(o[nt], pa0, pa1, pa2, pa3, FAU(vp[0]), FAU(vp[4 * 68]));
            }
        }
        __syncthreads();
        if (mt + 2 < 32) issue(mt + 2);
    }

    // epilogue: ctx rows, tf32-rounded (feeds out-proj MMA)
    const float il = 1.f / l_lo, ih = 1.f / l_hi;
    float* ob = ctx + ((size_t)(b * Nn) + n0 + rw + g) * INNERi + h * DHd + 2 * t;
#pragma unroll
    for (int nt = 0; nt < 8; nt++) {
        float2 vlo = {to_tf32(o[nt][0] * il), to_tf32(o[nt][1] * il)};
        float2 vhi = {to_tf32(o[nt][2] * ih), to_tf32(o[nt][3] * ih)};
        *(float2*)(ob + nt * 8) = vlo;
        *(float2*)(ob + 8 * (size_t)INNERi + nt * 8) = vhi;
    }
}

extern "C" void kernel_launch(void* const* d_in, const int* in_sizes, int n_in,
                              void* d_out, int out_size) {
    const float* x = (const float*)d_in[0];
    const float* x1 = (const float*)d_in[1];
    const float* am = (const float*)d_in[2];
    const float* dp = (const float*)d_in[3];
    const float* mp = (const float*)d_in[4];
    const float* Wqv = (const float*)d_in[5];
    const float* Wk = (const float*)d_in[6];
    const float* Wout = (const float*)d_in[7];
    const float* bout = (const float*)d_in[8];
    float* out = (float*)d_out;

    float *gx, *gx1, *gq, *gk, *gv, *gctx, *wqvt, *wkt, *wot;
    cudaGetSymbolAddress((void**)&gx, g_x);
    cudaGetSymbolAddress((void**)&gx1, g_x1);
    cudaGetSymbolAddress((void**)&gq, g_q);
    cudaGetSymbolAddress((void**)&gk, g_k);
    cudaGetSymbolAddress((void**)&gv, g_v);
    cudaGetSymbolAddress((void**)&gctx, g_ctx);
    cudaGetSymbolAddress((void**)&wqvt, g_wqvt);
    cudaGetSymbolAddress((void**)&wkt, g_wkt);
    cudaGetSymbolAddress((void**)&wot, g_wot);

    const int rows = Bb * Nn;  // 4096
    const int SM_GEMM = 2 * 9216 * 4;       // 73728
    const int SM_ATTN = 6 * 4352 * 4;       // 104448

    cudaFuncSetAttribute(mma_gemm<0>, cudaFuncAttributeMaxDynamicSharedMemorySize, SM_GEMM);
    cudaFuncSetAttribute(mma_gemm<1>, cudaFuncAttributeMaxDynamicSharedMemorySize, SM_GEMM);
    cudaFuncSetAttribute(mma_gemm<2>, cudaFuncAttributeMaxDynamicSharedMemorySize, SM_GEMM);
    cudaFuncSetAttribute(attn_mma, cudaFuncAttributeMaxDynamicSharedMemorySize, SM_ATTN);

    // prepass: tf32-round activations, transpose+round weights
    const int n4x = Bb * Nn * DIMd / 4;
    round_copy<<<(n4x + 255) / 256, 256>>>((const float4*)x, (float4*)gx, n4x);
    round_copy<<<(n4x + 255) / 256, 256>>>((const float4*)x1, (float4*)gx1, n4x);
    transposeW<<<dim3((2 * INNERi) / 32, DIMd / 32), 256>>>(Wqv, wqvt, DIMd, 2 * INNERi);
    transposeW<<<dim3(INNERi / 32, DIMd / 32), 256>>>(Wk, wkt, DIMd, INNERi);
    transposeW<<<dim3(DIMd / 32, INNERi / 32), 256>>>(Wout, wot, INNERi, DIMd);

    // projections
    mma_gemm<1><<<dim3((2 * INNERi) / 128, rows / 128), 256, SM_GEMM>>>(
        gx, wqvt, gq, gv, nullptr, 2 * INNERi, DIMd);
    mma_gemm<0><<<dim3(INNERi / 128, rows / 128), 256, SM_GEMM>>>(
        gx1, wkt, gk, nullptr, nullptr, INNERi, DIMd);

    // fused attention
    attn_mma<<<dim3(Nn / 128, Hh, Bb), 256, SM_ATTN>>>(gq, gk, gv, am, dp, mp, gctx);

    // output projection + bias
    mma_gemm<2><<<dim3(DIMd / 128, rows / 128), 256, SM_GEMM>>>(
        gctx, wot, out, nullptr, bout, DIMd, INNERi);
}